// round 11
// baseline (speedup 1.0000x reference)
#include <cuda_runtime.h>
#include <cuda_bf16.h>
#include <math.h>
#include <stdint.h>

// Problem constants
#define BB 16
#define SS 256
#define EE 256
#define HH 256
#define LL 9
#define MTOK (BB*SS)          // 4096 tokens
#define NG   2048             // 2 dirs * 4H
#define H2   512              // 2H

// ---------------- scratch (device globals; no allocs allowed) ----------------
__device__ float g_xa[MTOK * H2];        // 8 MB
__device__ float g_xb[MTOK * H2];        // 8 MB
__device__ float g_xg[MTOK * NG];        // 32 MB
__device__ float g_hb[2 * 2 * MTOK];     // [parity][dir][b][256]
// per (dir,step,sub) counters; 32-int (128B) stride so each sub-counter owns a line
__device__ int   g_ctr[2 * 256 * 4 * 32];    // 256 KB
__device__ float g_num[BB];

// ---------------- embedding gather ----------------
__global__ void embed_k(const int* __restrict__ ids,
                        const float* __restrict__ emb,
                        float* __restrict__ out)
{
    int m = blockIdx.x;          // token
    int e = threadIdx.x;         // 0..255
    out[m * EE + e] = emb[(size_t)ids[m] * EE + e];
}

// ---------------- big NT GEMM: Y[4096,2048] = X[4096,K] @ W[2048,K]^T + bias ---
// BM=128 BN=64 BK=16, 256 threads, thread tile 8x4
__global__ void gemm_xg(const float* __restrict__ X, int K,
                        const float* __restrict__ W,
                        const float* __restrict__ Bb,   // b + layer*4096
                        float* __restrict__ Y)
{
    __shared__ float Xs[16][132];
    __shared__ float Ws[16][68];
    const int m0 = blockIdx.y * 128;
    const int n0 = blockIdx.x * 64;
    const int t  = threadIdx.x;
    const int tx = t & 15, ty = t >> 4;

    float acc[8][4];
#pragma unroll
    for (int i = 0; i < 8; i++)
#pragma unroll
        for (int j = 0; j < 4; j++) acc[i][j] = 0.f;

    for (int kt = 0; kt < K; kt += 16) {
#pragma unroll
        for (int i = 0; i < 2; i++) {
            int fid = t + i * 256;            // 0..511
            int row = fid >> 2, c4 = fid & 3;
            float4 v = *(const float4*)&X[(size_t)(m0 + row) * K + kt + c4 * 4];
            Xs[c4 * 4 + 0][row] = v.x; Xs[c4 * 4 + 1][row] = v.y;
            Xs[c4 * 4 + 2][row] = v.z; Xs[c4 * 4 + 3][row] = v.w;
        }
        {
            int row = t >> 2, c4 = t & 3;
            float4 v = *(const float4*)&W[(size_t)(n0 + row) * K + kt + c4 * 4];
            Ws[c4 * 4 + 0][row] = v.x; Ws[c4 * 4 + 1][row] = v.y;
            Ws[c4 * 4 + 2][row] = v.z; Ws[c4 * 4 + 3][row] = v.w;
        }
        __syncthreads();
#pragma unroll
        for (int k = 0; k < 16; k++) {
            float a[8], bv[4];
            float4 a0 = *(const float4*)&Xs[k][ty * 8];
            float4 a1 = *(const float4*)&Xs[k][ty * 8 + 4];
            float4 b0 = *(const float4*)&Ws[k][tx * 4];
            a[0]=a0.x; a[1]=a0.y; a[2]=a0.z; a[3]=a0.w;
            a[4]=a1.x; a[5]=a1.y; a[6]=a1.z; a[7]=a1.w;
            bv[0]=b0.x; bv[1]=b0.y; bv[2]=b0.z; bv[3]=b0.w;
#pragma unroll
            for (int im = 0; im < 8; im++)
#pragma unroll
                for (int in2 = 0; in2 < 4; in2++)
                    acc[im][in2] += a[im] * bv[in2];
        }
        __syncthreads();
    }
    // epilogue: bias = b_ih + b_hh
    float bias[4];
#pragma unroll
    for (int in2 = 0; in2 < 4; in2++) {
        int n = n0 + tx * 4 + in2;
        int dd = n >> 10, r = n & 1023;
        bias[in2] = Bb[dd * 2048 + r] + Bb[dd * 2048 + 1024 + r];
    }
#pragma unroll
    for (int im = 0; im < 8; im++) {
        float4 o;
        o.x = acc[im][0] + bias[0];
        o.y = acc[im][1] + bias[1];
        o.z = acc[im][2] + bias[2];
        o.w = acc[im][3] + bias[3];
        *(float4*)&Y[(size_t)(m0 + ty * 8 + im) * NG + n0 + tx * 4] = o;
    }
}

// ---------------- zero barrier counters (256 KB) ----------------
__global__ void zero_ctr_k() {
    int i = blockIdx.x * blockDim.x + threadIdx.x;
    ((int4*)g_ctr)[i] = make_int4(0, 0, 0, 0);     // 16384 int4 = 65536 ints
}

// ---------------- recurrent LSTM scan, both directions ----------------
// 128 CTAs (64/dir). CTA owns 4 hidden units x 16 batches.
// R10 protocol, restructured to 512 threads (16 warps) for latency hiding:
// thread tile 2 rows x 4 batches x 16-interleaved-k. psum pitch 20 so the
// reduce is 4x LDS.128.
__global__ void __launch_bounds__(512, 1)
lstm_scan(const float* __restrict__ xg,
          const float* __restrict__ whh,   // [2][1024][256] this layer
          float* __restrict__ x_out)       // [4096][512]
{
    const int cta = blockIdx.x;
    const int d   = cta >> 6;
    const int j0  = (cta & 63) * 4;
    const int t   = threadIdx.x;

    const int kc = t & 15;          // k lane (interleaved: k = kc + 16*j)
    const int rg = (t >> 4) & 7;    // row group (2 rows)
    const int bg = t >> 7;          // batch group (4 b)

    __shared__ float hsm[16][260];
    __shared__ float psum[256 * 20];       // [dot][kc], pitch 20 (16B-aligned rows)
    __shared__ float G[16][17];
    __shared__ float cst[16][5];

    // preload W_hh slice into registers (constant across steps), interleaved k
    float wreg[2][16];
#pragma unroll
    for (int rr = 0; rr < 2; rr++) {
        int r    = rg * 2 + rr;                 // local row 0..15
        int grow = (r >> 2) * 256 + j0 + (r & 3);
        const float* wp = whh + ((size_t)d * 1024 + grow) * 256;
#pragma unroll
        for (int j = 0; j < 16; j++) wreg[rr][j] = wp[kc + 16 * j];
    }
    if (t < 64) cst[t & 15][t >> 4] = 0.f;   // c state [b][jj]
    __syncthreads();

    const int rX = t >> 4, bX = t & 15;               // for reduce (t<256)
    const int growX = (rX >> 2) * 256 + j0 + (rX & 3);
    const bool is_g_row = (rX >= 8 && rX < 12);       // g-gate rows

    for (int st = 0; st < SS; st++) {
        const int s_eff = d ? (SS - 1 - st) : st;

        // prefetch xg for this step (launch-constant; hidden under staging)
        float xval = 0.f;
        if (t < 256)
            xval = __ldcg(&xg[(size_t)(bX * SS + s_eff) * NG + d * 1024 + growX]);

        if (st > 0) {
            // stage h (prev step) from global ping-pong buffer (L2-coherent)
            const float* hsrc = g_hb + ((size_t)(st & 1) * 2 + d) * MTOK;
#pragma unroll
            for (int i = 0; i < 2; i++) {
                int f = t + i * 512;                 // float4 index 0..1023
                float4 v = __ldcg((const float4*)hsrc + f);
                int b = f >> 6, k = (f & 63) * 4;
                *(float4*)&hsm[b][k] = v;
            }
            __syncthreads();

            float acc[2][4];
#pragma unroll
            for (int rr = 0; rr < 2; rr++)
#pragma unroll
                for (int bb = 0; bb < 4; bb++) acc[rr][bb] = 0.f;
#pragma unroll
            for (int j = 0; j < 16; j++) {
                int k = kc + 16 * j;
                float hv[4];
#pragma unroll
                for (int bb = 0; bb < 4; bb++) hv[bb] = hsm[bg * 4 + bb][k];
#pragma unroll
                for (int rr = 0; rr < 2; rr++)
#pragma unroll
                    for (int bb = 0; bb < 4; bb++)
                        acc[rr][bb] += wreg[rr][j] * hv[bb];
            }
#pragma unroll
            for (int rr = 0; rr < 2; rr++)
#pragma unroll
                for (int bb = 0; bb < 4; bb++)
                    psum[((rg * 2 + rr) * 16 + (bg * 4 + bb)) * 20 + kc] = acc[rr][bb];
            __syncthreads();
        }

        // reduce k-partials + add xg + nonlinearity (threads 0..255, 1 dot each)
        if (t < 256) {
            float gate = xval;
            if (st > 0) {
                const float* pr = &psum[t * 20];
                float4 v0 = *(const float4*)&pr[0];
                float4 v1 = *(const float4*)&pr[4];
                float4 v2 = *(const float4*)&pr[8];
                float4 v3 = *(const float4*)&pr[12];
                gate += ((v0.x + v0.y) + (v0.z + v0.w)) + ((v1.x + v1.y) + (v1.z + v1.w))
                      + ((v2.x + v2.y) + (v2.z + v2.w)) + ((v3.x + v3.y) + (v3.z + v3.w));
            }
            float tv;
            if (is_g_row) tv = tanhf(gate);                    // g gate
            else          tv = 1.f / (1.f + expf(-gate));      // i, f, o gates
            G[rX][bX] = tv;
        }
        __syncthreads();

        // combine gates -> c,h for this CTA's 4 hidden units x 16 batches
        if (t < 64) {
            int jj = t >> 4, b = t & 15;
            float ig = G[jj][b], fg = G[4 + jj][b], tg = G[8 + jj][b], og = G[12 + jj][b];
            float c  = fg * cst[b][jj] + ig * tg;
            cst[b][jj] = c;
            float h = og * tanhf(c);
            int j = j0 + jj;
            __stcg(&g_hb[((size_t)((st + 1) & 1) * 2 + d) * MTOK + b * HH + j], h);
            x_out[(size_t)(b * SS + s_eff) * H2 + d * HH + j] = h;
        }

        // inter-CTA barrier (per direction): atomic arrive on 4 line-separated
        // sub-counters (16 deep each), volatile spin by 4 threads. R5 semantics.
        if (st < SS - 1) {
            __threadfence();
            __syncthreads();
            int* base = &g_ctr[((d * 256 + st) * 4) * 32];
            if (t == 0)
                atomicAdd(base + (cta & 3) * 32, 1);
            if (t < 4) {
                volatile int* p = base + t * 32;
                while (*p < 16) { }
            }
            __syncthreads();
        }
    }
}

// ---------------- LayerNorm + linear logits (warp per token) ----------------
__global__ void ln_logits(const float* __restrict__ X,
                          const float* __restrict__ lng,
                          const float* __restrict__ lnb,
                          const float* __restrict__ lw,
                          const float* __restrict__ lb,
                          float* __restrict__ out)
{
    __shared__ float slw[LL][H2];
    __shared__ float sg[H2], sb[H2];
    int t = threadIdx.x;
    for (int i = t; i < LL * H2; i += 256) ((float*)slw)[i] = lw[i];
    for (int i = t; i < H2; i += 256) { sg[i] = lng[i]; sb[i] = lnb[i]; }
    __syncthreads();

    int warp = t >> 5, lane = t & 31;
    int m = blockIdx.x * 8 + warp;

    float xv[16];
    const float* xr = X + (size_t)m * H2;
    float s1 = 0.f;
#pragma unroll
    for (int i = 0; i < 16; i++) { xv[i] = xr[i * 32 + lane]; s1 += xv[i]; }
#pragma unroll
    for (int o = 16; o; o >>= 1) s1 += __shfl_xor_sync(0xffffffffu, s1, o);
    float mu = s1 * (1.f / 512.f);
    float s2 = 0.f;
#pragma unroll
    for (int i = 0; i < 16; i++) { float dd = xv[i] - mu; s2 += dd * dd; }
#pragma unroll
    for (int o = 16; o; o >>= 1) s2 += __shfl_xor_sync(0xffffffffu, s2, o);
    float inv = rsqrtf(s2 * (1.f / 512.f) + 1e-5f);

    float xn[16];
#pragma unroll
    for (int i = 0; i < 16; i++) {
        int e = i * 32 + lane;
        xn[i] = (xv[i] - mu) * inv * sg[e] + sb[e];
    }
#pragma unroll
    for (int l = 0; l < LL; l++) {
        float p = 0.f;
#pragma unroll
        for (int i = 0; i < 16; i++) p += xn[i] * slw[l][i * 32 + lane];
#pragma unroll
        for (int o = 16; o; o >>= 1) p += __shfl_xor_sync(0xffffffffu, p, o);
        if (lane == 0) out[(size_t)m * LL + l] = p + lb[l];
    }
}

// ---------------- CRF numerator (one lane per batch) ----------------
__global__ void crf_num(const float* __restrict__ lg,
                        const int* __restrict__ labels,
                        const int* __restrict__ mask,
                        const float* __restrict__ cs,
                        const float* __restrict__ ce,
                        const float* __restrict__ tr)
{
    int b = threadIdx.x;
    if (b >= BB) return;
    const int* lab = labels + b * SS;
    const int* mk  = mask + b * SS;
    const float* e = lg + (size_t)b * SS * LL;
    int tp = lab[0];
    float num = cs[tp] + e[tp];
    int msum = mk[0];
    for (int s = 1; s < SS; s++) {
        int tc = lab[s];
        float m = (float)mk[s];
        num += (tr[tp * LL + tc] + e[s * LL + tc]) * m;
        msum += mk[s];
        tp = tc;
    }
    num += ce[lab[msum - 1]];
    g_num[b] = num;
}

// ---------------- CRF denominator + loss (warp per batch) ----------------
__global__ void crf_denom(const float* __restrict__ lg,
                          const int* __restrict__ mask,
                          const float* __restrict__ cs,
                          const float* __restrict__ ce,
                          const float* __restrict__ tr,
                          float* __restrict__ loss1,
                          float* __restrict__ loss2)
{
    __shared__ float parts[BB];
    __shared__ float str[81];
    int t = threadIdx.x;
    if (t < 81) str[t] = tr[t];
    __syncthreads();

    int warp = t >> 5, lane = t & 31;
    if (warp < BB) {
        int b = warp;
        const float* e = lg + (size_t)b * SS * LL;
        int jj = (lane < LL) ? lane : (LL - 1);
        float alpha = cs[jj] + e[jj];
        for (int s = 1; s < SS; s++) {
            float tv[LL];
            float mx = -1e30f;
#pragma unroll
            for (int i = 0; i < LL; i++) {
                float ai = __shfl_sync(0xffffffffu, alpha, i);
                float v = ai + str[i * LL + jj];
                tv[i] = v;
                mx = fmaxf(mx, v);
            }
            float ssum = 0.f;
#pragma unroll
            for (int i = 0; i < LL; i++) ssum += expf(tv[i] - mx);
            float nxt = mx + logf(ssum) + e[s * LL + jj];
            if (mask[b * SS + s] > 0) alpha = nxt;
        }
        float val = (lane < LL) ? (alpha + ce[jj]) : -1e30f;
        float mx = val;
#pragma unroll
        for (int o = 16; o; o >>= 1) mx = fmaxf(mx, __shfl_xor_sync(0xffffffffu, mx, o));
        float se = expf(val - mx);
#pragma unroll
        for (int o = 16; o; o >>= 1) se += __shfl_xor_sync(0xffffffffu, se, o);
        if (lane == 0) parts[b] = g_num[b] - (mx + logf(se));
    }
    __syncthreads();
    if (t == 0) {
        float s = 0.f;
        for (int i = 0; i < BB; i++) s += parts[i];
        float loss = -s;
        *loss1 = loss;
        if (loss2 != loss1) *loss2 = loss;
    }
}

// ---------------- host launcher ----------------
extern "C" void kernel_launch(void* const* d_in, const int* in_sizes, int n_in,
                              void* d_out, int out_size)
{
    const int*   ids    = (const int*)d_in[0];
    const int*   amask  = (const int*)d_in[1];
    const int*   labels = (const int*)d_in[2];
    const float* emb    = (const float*)d_in[3];
    const float* w_l0   = (const float*)d_in[4];
    const float* w_rest = (const float*)d_in[5];
    const float* w_hh   = (const float*)d_in[6];
    const float* bvec   = (const float*)d_in[7];
    const float* ln_g   = (const float*)d_in[8];
    const float* ln_b   = (const float*)d_in[9];
    const float* lin_w  = (const float*)d_in[10];
    const float* lin_b  = (const float*)d_in[11];
    const float* cstart = (const float*)d_in[12];
    const float* cend   = (const float*)d_in[13];
    const float* ctrans = (const float*)d_in[14];

    float *xa, *xb, *xgp;
    cudaGetSymbolAddress((void**)&xa,  g_xa);
    cudaGetSymbolAddress((void**)&xb,  g_xb);
    cudaGetSymbolAddress((void**)&xgp, g_xg);

    float* outF = (float*)d_out;

    embed_k<<<MTOK, EE>>>(ids, emb, xa);

    float* cur = xa;
    float* nxt = xb;
    for (int layer = 0; layer < 4; layer++) {
        const float* W = (layer == 0) ? w_l0 : (w_rest + (size_t)(layer - 1) * 2 * 1024 * 512);
        int K = (layer == 0) ? EE : H2;
        gemm_xg<<<dim3(NG / 64, MTOK / 128), 256>>>(cur, K, W, bvec + layer * 4096, xgp);
        zero_ctr_k<<<64, 256>>>();   // 64*256 int4 = 65536 ints
        lstm_scan<<<128, 512>>>(xgp, w_hh + (size_t)layer * 2 * 1024 * 256, nxt);
        float* tmp = cur; cur = nxt; nxt = tmp;
    }

    ln_logits<<<MTOK / 8, 256>>>(cur, ln_g, ln_b, lin_w, lin_b, outF);

    crf_num<<<1, 32>>>(outF, labels, amask, cstart, cend, ctrans);

    float* lp1 = outF + (size_t)MTOK * LL;          // expected loss slot (36864)
    float* lp2 = outF + (out_size - 1);             // defensive: last element
    crf_denom<<<1, 512>>>(outF, amask, cstart, cend, ctrans, lp1, lp2);
}

// round 14
// speedup vs baseline: 1.1325x; 1.1325x over previous
#include <cuda_runtime.h>
#include <cuda_bf16.h>
#include <math.h>
#include <stdint.h>

// Problem constants
#define BB 16
#define SS 256
#define EE 256
#define HH 256
#define LL 9
#define MTOK (BB*SS)          // 4096 tokens
#define NG   2048             // 2 dirs * 4H
#define H2   512              // 2H

// ---------------- scratch (device globals; no allocs allowed) ----------------
__device__ float g_xa[MTOK * H2];        // 8 MB
__device__ float g_xb[MTOK * H2];        // 8 MB
__device__ float g_xg[MTOK * NG];        // 32 MB
__device__ float g_hb[2 * 2 * MTOK];     // [parity][dir][b][256]
// per (dir,step,sub) counters; 32-int (128B) stride so each sub-counter owns a line
__device__ int   g_ctr[2 * 256 * 4 * 32];    // 256 KB
__device__ float g_num[BB];

// ---------------- embedding gather ----------------
__global__ void embed_k(const int* __restrict__ ids,
                        const float* __restrict__ emb,
                        float* __restrict__ out)
{
    int m = blockIdx.x;          // token
    int e = threadIdx.x;         // 0..255
    out[m * EE + e] = emb[(size_t)ids[m] * EE + e];
}

// ---------------- big NT GEMM: Y[4096,2048] = X[4096,K] @ W[2048,K]^T + bias ---
// BM=128 BN=64 BK=16, 256 threads, thread tile 8x4
__global__ void gemm_xg(const float* __restrict__ X, int K,
                        const float* __restrict__ W,
                        const float* __restrict__ Bb,   // b + layer*4096
                        float* __restrict__ Y)
{
    __shared__ float Xs[16][132];
    __shared__ float Ws[16][68];
    const int m0 = blockIdx.y * 128;
    const int n0 = blockIdx.x * 64;
    const int t  = threadIdx.x;
    const int tx = t & 15, ty = t >> 4;

    float acc[8][4];
#pragma unroll
    for (int i = 0; i < 8; i++)
#pragma unroll
        for (int j = 0; j < 4; j++) acc[i][j] = 0.f;

    for (int kt = 0; kt < K; kt += 16) {
#pragma unroll
        for (int i = 0; i < 2; i++) {
            int fid = t + i * 256;            // 0..511
            int row = fid >> 2, c4 = fid & 3;
            float4 v = *(const float4*)&X[(size_t)(m0 + row) * K + kt + c4 * 4];
            Xs[c4 * 4 + 0][row] = v.x; Xs[c4 * 4 + 1][row] = v.y;
            Xs[c4 * 4 + 2][row] = v.z; Xs[c4 * 4 + 3][row] = v.w;
        }
        {
            int row = t >> 2, c4 = t & 3;
            float4 v = *(const float4*)&W[(size_t)(n0 + row) * K + kt + c4 * 4];
            Ws[c4 * 4 + 0][row] = v.x; Ws[c4 * 4 + 1][row] = v.y;
            Ws[c4 * 4 + 2][row] = v.z; Ws[c4 * 4 + 3][row] = v.w;
        }
        __syncthreads();
#pragma unroll
        for (int k = 0; k < 16; k++) {
            float a[8], bv[4];
            float4 a0 = *(const float4*)&Xs[k][ty * 8];
            float4 a1 = *(const float4*)&Xs[k][ty * 8 + 4];
            float4 b0 = *(const float4*)&Ws[k][tx * 4];
            a[0]=a0.x; a[1]=a0.y; a[2]=a0.z; a[3]=a0.w;
            a[4]=a1.x; a[5]=a1.y; a[6]=a1.z; a[7]=a1.w;
            bv[0]=b0.x; bv[1]=b0.y; bv[2]=b0.z; bv[3]=b0.w;
#pragma unroll
            for (int im = 0; im < 8; im++)
#pragma unroll
                for (int in2 = 0; in2 < 4; in2++)
                    acc[im][in2] += a[im] * bv[in2];
        }
        __syncthreads();
    }
    // epilogue: bias = b_ih + b_hh
    float bias[4];
#pragma unroll
    for (int in2 = 0; in2 < 4; in2++) {
        int n = n0 + tx * 4 + in2;
        int dd = n >> 10, r = n & 1023;
        bias[in2] = Bb[dd * 2048 + r] + Bb[dd * 2048 + 1024 + r];
    }
#pragma unroll
    for (int im = 0; im < 8; im++) {
        float4 o;
        o.x = acc[im][0] + bias[0];
        o.y = acc[im][1] + bias[1];
        o.z = acc[im][2] + bias[2];
        o.w = acc[im][3] + bias[3];
        *(float4*)&Y[(size_t)(m0 + ty * 8 + im) * NG + n0 + tx * 4] = o;
    }
}

// ---------------- zero barrier counters (256 KB) ----------------
__global__ void zero_ctr_k() {
    int i = blockIdx.x * blockDim.x + threadIdx.x;
    ((int4*)g_ctr)[i] = make_int4(0, 0, 0, 0);     // 16384 int4 = 65536 ints
}

// ---------------- recurrent LSTM scan, both directions ----------------
// 128 CTAs (64/dir). CTA owns 4 hidden units x 16 batches.
// R10 (passing, 3393us) verbatim; SINGLE change: fast-math sigmoid
// (1/(1+__expf(-x))) for i/f/o gates. tanh stays libm (cancellation safety).
__global__ void __launch_bounds__(256, 1)
lstm_scan(const float* __restrict__ xg,
          const float* __restrict__ whh,   // [2][1024][256] this layer
          float* __restrict__ x_out)       // [4096][512]
{
    const int cta = blockIdx.x;
    const int d   = cta >> 6;
    const int j0  = (cta & 63) * 4;
    const int t   = threadIdx.x;

    const int kc = t & 15;          // k lane (interleaved: k = kc + 16*j)
    const int rg = (t >> 4) & 3;    // row group (4 rows)
    const int bg = t >> 6;          // batch group (4 b)

    __shared__ float hsm[16][260];
    __shared__ float psum[256][17];
    __shared__ float G[16][17];
    __shared__ float cst[16][5];

    // preload W_hh slice into registers (constant across steps), interleaved k
    float wreg[4][16];
#pragma unroll
    for (int rr = 0; rr < 4; rr++) {
        int r    = rg * 4 + rr;                 // local row 0..15
        int grow = (r >> 2) * 256 + j0 + (r & 3);
        const float* wp = whh + ((size_t)d * 1024 + grow) * 256;
#pragma unroll
        for (int j = 0; j < 16; j++) wreg[rr][j] = wp[kc + 16 * j];
    }
    if (t < 64) cst[t & 15][t >> 4] = 0.f;   // c state [b][jj]
    __syncthreads();

    const int rX = t >> 4, bX = t & 15;
    const int growX = (rX >> 2) * 256 + j0 + (rX & 3);
    const bool is_g_row = (rX >= 8 && rX < 12);     // warp-uniform

    for (int st = 0; st < SS; st++) {
        const int s_eff = d ? (SS - 1 - st) : st;

        // prefetch xg for this step (launch-constant; hidden under staging)
        float xval = __ldcg(&xg[(size_t)(bX * SS + s_eff) * NG + d * 1024 + growX]);

        if (st > 0) {
            // stage h (prev step) from global ping-pong buffer (L2-coherent)
            const float* hsrc = g_hb + ((size_t)(st & 1) * 2 + d) * MTOK;
#pragma unroll
            for (int i = 0; i < 4; i++) {
                int f = t + i * 256;                 // float4 index 0..1023
                float4 v = __ldcg((const float4*)hsrc + f);
                int b = f >> 6, k = (f & 63) * 4;
                *(float4*)&hsm[b][k] = v;
            }
            __syncthreads();

            float acc[4][4];
#pragma unroll
            for (int rr = 0; rr < 4; rr++)
#pragma unroll
                for (int bb = 0; bb < 4; bb++) acc[rr][bb] = 0.f;
#pragma unroll
            for (int j = 0; j < 16; j++) {
                int k = kc + 16 * j;
                float hv[4];
#pragma unroll
                for (int bb = 0; bb < 4; bb++) hv[bb] = hsm[bg * 4 + bb][k];
#pragma unroll
                for (int rr = 0; rr < 4; rr++)
#pragma unroll
                    for (int bb = 0; bb < 4; bb++)
                        acc[rr][bb] += wreg[rr][j] * hv[bb];
            }
#pragma unroll
            for (int rr = 0; rr < 4; rr++)
#pragma unroll
                for (int bb = 0; bb < 4; bb++)
                    psum[(rg * 4 + rr) * 16 + (bg * 4 + bb)][kc] = acc[rr][bb];
            __syncthreads();
        }

        // reduce k-partials + add xg + nonlinearity (256 threads, 1 gate each)
        {
            float gate = xval;
            if (st > 0) {
                float s = 0.f;
#pragma unroll
                for (int i = 0; i < 16; i++) s += psum[t][i];
                gate += s;
            }
            float tv;
            if (is_g_row) tv = tanhf(gate);                        // g gate (libm)
            else          tv = 1.f / (1.f + __expf(-gate));        // i,f,o (fast exp)
            G[rX][bX] = tv;
        }
        __syncthreads();

        // combine gates -> c,h for this CTA's 4 hidden units x 16 batches
        if (t < 64) {
            int jj = t >> 4, b = t & 15;
            float ig = G[jj][b], fg = G[4 + jj][b], tg = G[8 + jj][b], og = G[12 + jj][b];
            float c  = fg * cst[b][jj] + ig * tg;
            cst[b][jj] = c;
            float h = og * tanhf(c);
            int j = j0 + jj;
            __stcg(&g_hb[((size_t)((st + 1) & 1) * 2 + d) * MTOK + b * HH + j], h);
            x_out[(size_t)(b * SS + s_eff) * H2 + d * HH + j] = h;
        }

        // inter-CTA barrier (per direction): atomic arrive on 4 line-separated
        // sub-counters (16 deep each), volatile spin by 4 threads. R5 semantics.
        if (st < SS - 1) {
            __threadfence();
            __syncthreads();
            int* base = &g_ctr[((d * 256 + st) * 4) * 32];
            if (t == 0)
                atomicAdd(base + (cta & 3) * 32, 1);
            if (t < 4) {
                volatile int* p = base + t * 32;
                while (*p < 16) { }
            }
            __syncthreads();
        }
    }
}

// ---------------- LayerNorm + linear logits (warp per token) ----------------
__global__ void ln_logits(const float* __restrict__ X,
                          const float* __restrict__ lng,
                          const float* __restrict__ lnb,
                          const float* __restrict__ lw,
                          const float* __restrict__ lb,
                          float* __restrict__ out)
{
    __shared__ float slw[LL][H2];
    __shared__ float sg[H2], sb[H2];
    int t = threadIdx.x;
    for (int i = t; i < LL * H2; i += 256) ((float*)slw)[i] = lw[i];
    for (int i = t; i < H2; i += 256) { sg[i] = lng[i]; sb[i] = lnb[i]; }
    __syncthreads();

    int warp = t >> 5, lane = t & 31;
    int m = blockIdx.x * 8 + warp;

    float xv[16];
    const float* xr = X + (size_t)m * H2;
    float s1 = 0.f;
#pragma unroll
    for (int i = 0; i < 16; i++) { xv[i] = xr[i * 32 + lane]; s1 += xv[i]; }
#pragma unroll
    for (int o = 16; o; o >>= 1) s1 += __shfl_xor_sync(0xffffffffu, s1, o);
    float mu = s1 * (1.f / 512.f);
    float s2 = 0.f;
#pragma unroll
    for (int i = 0; i < 16; i++) { float dd = xv[i] - mu; s2 += dd * dd; }
#pragma unroll
    for (int o = 16; o; o >>= 1) s2 += __shfl_xor_sync(0xffffffffu, s2, o);
    float inv = rsqrtf(s2 * (1.f / 512.f) + 1e-5f);

    float xn[16];
#pragma unroll
    for (int i = 0; i < 16; i++) {
        int e = i * 32 + lane;
        xn[i] = (xv[i] - mu) * inv * sg[e] + sb[e];
    }
#pragma unroll
    for (int l = 0; l < LL; l++) {
        float p = 0.f;
#pragma unroll
        for (int i = 0; i < 16; i++) p += xn[i] * slw[l][i * 32 + lane];
#pragma unroll
        for (int o = 16; o; o >>= 1) p += __shfl_xor_sync(0xffffffffu, p, o);
        if (lane == 0) out[(size_t)m * LL + l] = p + lb[l];
    }
}

// ---------------- CRF numerator (one lane per batch) ----------------
__global__ void crf_num(const float* __restrict__ lg,
                        const int* __restrict__ labels,
                        const int* __restrict__ mask,
                        const float* __restrict__ cs,
                        const float* __restrict__ ce,
                        const float* __restrict__ tr)
{
    int b = threadIdx.x;
    if (b >= BB) return;
    const int* lab = labels + b * SS;
    const int* mk  = mask + b * SS;
    const float* e = lg + (size_t)b * SS * LL;
    int tp = lab[0];
    float num = cs[tp] + e[tp];
    int msum = mk[0];
    for (int s = 1; s < SS; s++) {
        int tc = lab[s];
        float m = (float)mk[s];
        num += (tr[tp * LL + tc] + e[s * LL + tc]) * m;
        msum += mk[s];
        tp = tc;
    }
    num += ce[lab[msum - 1]];
    g_num[b] = num;
}

// ---------------- CRF denominator + loss (warp per batch) ----------------
__global__ void crf_denom(const float* __restrict__ lg,
                          const int* __restrict__ mask,
                          const float* __restrict__ cs,
                          const float* __restrict__ ce,
                          const float* __restrict__ tr,
                          float* __restrict__ loss1,
                          float* __restrict__ loss2)
{
    __shared__ float parts[BB];
    __shared__ float str[81];
    int t = threadIdx.x;
    if (t < 81) str[t] = tr[t];
    __syncthreads();

    int warp = t >> 5, lane = t & 31;
    if (warp < BB) {
        int b = warp;
        const float* e = lg + (size_t)b * SS * LL;
        int jj = (lane < LL) ? lane : (LL - 1);
        float alpha = cs[jj] + e[jj];
        for (int s = 1; s < SS; s++) {
            float tv[LL];
            float mx = -1e30f;
#pragma unroll
            for (int i = 0; i < LL; i++) {
                float ai = __shfl_sync(0xffffffffu, alpha, i);
                float v = ai + str[i * LL + jj];
                tv[i] = v;
                mx = fmaxf(mx, v);
            }
            float ssum = 0.f;
#pragma unroll
            for (int i = 0; i < LL; i++) ssum += expf(tv[i] - mx);
            float nxt = mx + logf(ssum) + e[s * LL + jj];
            if (mask[b * SS + s] > 0) alpha = nxt;
        }
        float val = (lane < LL) ? (alpha + ce[jj]) : -1e30f;
        float mx = val;
#pragma unroll
        for (int o = 16; o; o >>= 1) mx = fmaxf(mx, __shfl_xor_sync(0xffffffffu, mx, o));
        float se = expf(val - mx);
#pragma unroll
        for (int o = 16; o; o >>= 1) se += __shfl_xor_sync(0xffffffffu, se, o);
        if (lane == 0) parts[b] = g_num[b] - (mx + logf(se));
    }
    __syncthreads();
    if (t == 0) {
        float s = 0.f;
        for (int i = 0; i < BB; i++) s += parts[i];
        float loss = -s;
        *loss1 = loss;
        if (loss2 != loss1) *loss2 = loss;
    }
}

// ---------------- host launcher ----------------
extern "C" void kernel_launch(void* const* d_in, const int* in_sizes, int n_in,
                              void* d_out, int out_size)
{
    const int*   ids    = (const int*)d_in[0];
    const int*   amask  = (const int*)d_in[1];
    const int*   labels = (const int*)d_in[2];
    const float* emb    = (const float*)d_in[3];
    const float* w_l0   = (const float*)d_in[4];
    const float* w_rest = (const float*)d_in[5];
    const float* w_hh   = (const float*)d_in[6];
    const float* bvec   = (const float*)d_in[7];
    const float* ln_g   = (const float*)d_in[8];
    const float* ln_b   = (const float*)d_in[9];
    const float* lin_w  = (const float*)d_in[10];
    const float* lin_b  = (const float*)d_in[11];
    const float* cstart = (const float*)d_in[12];
    const float* cend   = (const float*)d_in[13];
    const float* ctrans = (const float*)d_in[14];

    float *xa, *xb, *xgp;
    cudaGetSymbolAddress((void**)&xa,  g_xa);
    cudaGetSymbolAddress((void**)&xb,  g_xb);
    cudaGetSymbolAddress((void**)&xgp, g_xg);

    float* outF = (float*)d_out;

    embed_k<<<MTOK, EE>>>(ids, emb, xa);

    float* cur = xa;
    float* nxt = xb;
    for (int layer = 0; layer < 4; layer++) {
        const float* W = (layer == 0) ? w_l0 : (w_rest + (size_t)(layer - 1) * 2 * 1024 * 512);
        int K = (layer == 0) ? EE : H2;
        gemm_xg<<<dim3(NG / 64, MTOK / 128), 256>>>(cur, K, W, bvec + layer * 4096, xgp);
        zero_ctr_k<<<64, 256>>>();   // 64*256 int4 = 65536 ints
        lstm_scan<<<128, 256>>>(xgp, w_hh + (size_t)layer * 2 * 1024 * 256, nxt);
        float* tmp = cur; cur = nxt; nxt = tmp;
    }

    ln_logits<<<MTOK / 8, 256>>>(cur, ln_g, ln_b, lin_w, lin_b, outF);

    crf_num<<<1, 32>>>(outF, labels, amask, cstart, cend, ctrans);

    float* lp1 = outF + (size_t)MTOK * LL;          // expected loss slot (36864)
    float* lp2 = outF + (out_size - 1);             // defensive: last element
    crf_denom<<<1, 512>>>(outF, amask, cstart, cend, ctrans, lp1, lp2);
}

// round 15
// speedup vs baseline: 1.1352x; 1.0024x over previous
#include <cuda_runtime.h>
#include <cuda_bf16.h>
#include <math.h>
#include <stdint.h>

// Problem constants
#define BB 16
#define SS 256
#define EE 256
#define HH 256
#define LL 9
#define MTOK (BB*SS)          // 4096 tokens
#define NG   2048             // 2 dirs * 4H
#define H2   512              // 2H

// ---------------- scratch (device globals; no allocs allowed) ----------------
__device__ float g_xa[MTOK * H2];        // 8 MB
__device__ float g_xb[MTOK * H2];        // 8 MB
__device__ float g_xg[MTOK * NG];        // 32 MB
__device__ float g_hb[2 * 2 * MTOK];     // [parity][dir][b][256]
// per (dir,step,sub) counters; 32-int (128B) stride so each sub-counter owns a line
__device__ int   g_ctr[2 * 256 * 4 * 32];    // 256 KB
__device__ float g_num[BB];

// ---------------- f32x2 helpers (bit-exact packed FMA) ----------------
__device__ __forceinline__ uint64_t pack2(float lo, float hi) {
    uint64_t r; asm("mov.b64 %0,{%1,%2};" : "=l"(r) : "f"(lo), "f"(hi)); return r;
}
__device__ __forceinline__ void unpack2(uint64_t v, float& lo, float& hi) {
    asm("mov.b64 {%0,%1},%2;" : "=f"(lo), "=f"(hi) : "l"(v));
}
__device__ __forceinline__ uint64_t fma2(uint64_t a, uint64_t b, uint64_t c) {
    uint64_t d; asm("fma.rn.f32x2 %0,%1,%2,%3;" : "=l"(d) : "l"(a), "l"(b), "l"(c)); return d;
}

// ---------------- embedding gather ----------------
__global__ void embed_k(const int* __restrict__ ids,
                        const float* __restrict__ emb,
                        float* __restrict__ out)
{
    int m = blockIdx.x;          // token
    int e = threadIdx.x;         // 0..255
    out[m * EE + e] = emb[(size_t)ids[m] * EE + e];
}

// ---------------- big NT GEMM: Y[4096,2048] = X[4096,K] @ W[2048,K]^T + bias ---
// BM=128 BN=64 BK=16, 256 threads, thread tile 8x4
__global__ void gemm_xg(const float* __restrict__ X, int K,
                        const float* __restrict__ W,
                        const float* __restrict__ Bb,   // b + layer*4096
                        float* __restrict__ Y)
{
    __shared__ float Xs[16][132];
    __shared__ float Ws[16][68];
    const int m0 = blockIdx.y * 128;
    const int n0 = blockIdx.x * 64;
    const int t  = threadIdx.x;
    const int tx = t & 15, ty = t >> 4;

    float acc[8][4];
#pragma unroll
    for (int i = 0; i < 8; i++)
#pragma unroll
        for (int j = 0; j < 4; j++) acc[i][j] = 0.f;

    for (int kt = 0; kt < K; kt += 16) {
#pragma unroll
        for (int i = 0; i < 2; i++) {
            int fid = t + i * 256;            // 0..511
            int row = fid >> 2, c4 = fid & 3;
            float4 v = *(const float4*)&X[(size_t)(m0 + row) * K + kt + c4 * 4];
            Xs[c4 * 4 + 0][row] = v.x; Xs[c4 * 4 + 1][row] = v.y;
            Xs[c4 * 4 + 2][row] = v.z; Xs[c4 * 4 + 3][row] = v.w;
        }
        {
            int row = t >> 2, c4 = t & 3;
            float4 v = *(const float4*)&W[(size_t)(n0 + row) * K + kt + c4 * 4];
            Ws[c4 * 4 + 0][row] = v.x; Ws[c4 * 4 + 1][row] = v.y;
            Ws[c4 * 4 + 2][row] = v.z; Ws[c4 * 4 + 3][row] = v.w;
        }
        __syncthreads();
#pragma unroll
        for (int k = 0; k < 16; k++) {
            float a[8], bv[4];
            float4 a0 = *(const float4*)&Xs[k][ty * 8];
            float4 a1 = *(const float4*)&Xs[k][ty * 8 + 4];
            float4 b0 = *(const float4*)&Ws[k][tx * 4];
            a[0]=a0.x; a[1]=a0.y; a[2]=a0.z; a[3]=a0.w;
            a[4]=a1.x; a[5]=a1.y; a[6]=a1.z; a[7]=a1.w;
            bv[0]=b0.x; bv[1]=b0.y; bv[2]=b0.z; bv[3]=b0.w;
#pragma unroll
            for (int im = 0; im < 8; im++)
#pragma unroll
                for (int in2 = 0; in2 < 4; in2++)
                    acc[im][in2] += a[im] * bv[in2];
        }
        __syncthreads();
    }
    // epilogue: bias = b_ih + b_hh
    float bias[4];
#pragma unroll
    for (int in2 = 0; in2 < 4; in2++) {
        int n = n0 + tx * 4 + in2;
        int dd = n >> 10, r = n & 1023;
        bias[in2] = Bb[dd * 2048 + r] + Bb[dd * 2048 + 1024 + r];
    }
#pragma unroll
    for (int im = 0; im < 8; im++) {
        float4 o;
        o.x = acc[im][0] + bias[0];
        o.y = acc[im][1] + bias[1];
        o.z = acc[im][2] + bias[2];
        o.w = acc[im][3] + bias[3];
        *(float4*)&Y[(size_t)(m0 + ty * 8 + im) * NG + n0 + tx * 4] = o;
    }
}

// ---------------- zero barrier counters (256 KB) ----------------
__global__ void zero_ctr_k() {
    int i = blockIdx.x * blockDim.x + threadIdx.x;
    ((int4*)g_ctr)[i] = make_int4(0, 0, 0, 0);     // 16384 int4 = 65536 ints
}

// ---------------- recurrent LSTM scan, both directions ----------------
// 128 CTAs (64/dir). CTA owns 4 hidden units x 16 batches.
// R14 (passing, 3391us) verbatim; SINGLE change: the h@W_hh matmul uses
// packed fma.rn.f32x2 (rows paired, hv duplicated) — bit-exact, halves
// FMA-pipe issue count. Barrier untouched.
__global__ void __launch_bounds__(256, 1)
lstm_scan(const float* __restrict__ xg,
          const float* __restrict__ whh,   // [2][1024][256] this layer
          float* __restrict__ x_out)       // [4096][512]
{
    const int cta = blockIdx.x;
    const int d   = cta >> 6;
    const int j0  = (cta & 63) * 4;
    const int t   = threadIdx.x;

    const int kc = t & 15;          // k lane (interleaved: k = kc + 16*j)
    const int rg = (t >> 4) & 3;    // row group (4 rows)
    const int bg = t >> 6;          // batch group (4 b)

    __shared__ float hsm[16][260];
    __shared__ float psum[256][17];
    __shared__ float G[16][17];
    __shared__ float cst[16][5];

    // preload W_hh slice as row-paired f32x2 (constant across steps), interleaved k
    uint64_t w2[2][16];
#pragma unroll
    for (int p = 0; p < 2; p++) {
        int r0 = rg * 4 + 2 * p, r1 = r0 + 1;
        int grow0 = (r0 >> 2) * 256 + j0 + (r0 & 3);
        int grow1 = (r1 >> 2) * 256 + j0 + (r1 & 3);
        const float* wp0 = whh + ((size_t)d * 1024 + grow0) * 256;
        const float* wp1 = whh + ((size_t)d * 1024 + grow1) * 256;
#pragma unroll
        for (int j = 0; j < 16; j++)
            w2[p][j] = pack2(wp0[kc + 16 * j], wp1[kc + 16 * j]);
    }
    if (t < 64) cst[t & 15][t >> 4] = 0.f;   // c state [b][jj]
    __syncthreads();

    const int rX = t >> 4, bX = t & 15;
    const int growX = (rX >> 2) * 256 + j0 + (rX & 3);
    const bool is_g_row = (rX >= 8 && rX < 12);     // warp-uniform

    for (int st = 0; st < SS; st++) {
        const int s_eff = d ? (SS - 1 - st) : st;

        // prefetch xg for this step (launch-constant; hidden under staging)
        float xval = __ldcg(&xg[(size_t)(bX * SS + s_eff) * NG + d * 1024 + growX]);

        if (st > 0) {
            // stage h (prev step) from global ping-pong buffer (L2-coherent)
            const float* hsrc = g_hb + ((size_t)(st & 1) * 2 + d) * MTOK;
#pragma unroll
            for (int i = 0; i < 4; i++) {
                int f = t + i * 256;                 // float4 index 0..1023
                float4 v = __ldcg((const float4*)hsrc + f);
                int b = f >> 6, k = (f & 63) * 4;
                *(float4*)&hsm[b][k] = v;
            }
            __syncthreads();

            uint64_t acc2[2][4];
#pragma unroll
            for (int p = 0; p < 2; p++)
#pragma unroll
                for (int bb = 0; bb < 4; bb++) acc2[p][bb] = 0ull;
#pragma unroll
            for (int j = 0; j < 16; j++) {
                int k = kc + 16 * j;
                uint64_t hd[4];
#pragma unroll
                for (int bb = 0; bb < 4; bb++) {
                    float hv = hsm[bg * 4 + bb][k];
                    hd[bb] = pack2(hv, hv);
                }
#pragma unroll
                for (int p = 0; p < 2; p++)
#pragma unroll
                    for (int bb = 0; bb < 4; bb++)
                        acc2[p][bb] = fma2(w2[p][j], hd[bb], acc2[p][bb]);
            }
#pragma unroll
            for (int p = 0; p < 2; p++)
#pragma unroll
                for (int bb = 0; bb < 4; bb++) {
                    float lo, hi;
                    unpack2(acc2[p][bb], lo, hi);
                    psum[(rg * 4 + 2 * p + 0) * 16 + (bg * 4 + bb)][kc] = lo;
                    psum[(rg * 4 + 2 * p + 1) * 16 + (bg * 4 + bb)][kc] = hi;
                }
            __syncthreads();
        }

        // reduce k-partials + add xg + nonlinearity (256 threads, 1 gate each)
        {
            float gate = xval;
            if (st > 0) {
                float s = 0.f;
#pragma unroll
                for (int i = 0; i < 16; i++) s += psum[t][i];
                gate += s;
            }
            float tv;
            if (is_g_row) tv = tanhf(gate);                        // g gate (libm)
            else          tv = 1.f / (1.f + __expf(-gate));        // i,f,o (fast exp)
            G[rX][bX] = tv;
        }
        __syncthreads();

        // combine gates -> c,h for this CTA's 4 hidden units x 16 batches
        if (t < 64) {
            int jj = t >> 4, b = t & 15;
            float ig = G[jj][b], fg = G[4 + jj][b], tg = G[8 + jj][b], og = G[12 + jj][b];
            float c  = fg * cst[b][jj] + ig * tg;
            cst[b][jj] = c;
            float h = og * tanhf(c);
            int j = j0 + jj;
            __stcg(&g_hb[((size_t)((st + 1) & 1) * 2 + d) * MTOK + b * HH + j], h);
            x_out[(size_t)(b * SS + s_eff) * H2 + d * HH + j] = h;
        }

        // inter-CTA barrier (per direction): atomic arrive on 4 line-separated
        // sub-counters (16 deep each), volatile spin by 4 threads. R5 semantics.
        if (st < SS - 1) {
            __threadfence();
            __syncthreads();
            int* base = &g_ctr[((d * 256 + st) * 4) * 32];
            if (t == 0)
                atomicAdd(base + (cta & 3) * 32, 1);
            if (t < 4) {
                volatile int* p = base + t * 32;
                while (*p < 16) { }
            }
            __syncthreads();
        }
    }
}

// ---------------- LayerNorm + linear logits (warp per token) ----------------
__global__ void ln_logits(const float* __restrict__ X,
                          const float* __restrict__ lng,
                          const float* __restrict__ lnb,
                          const float* __restrict__ lw,
                          const float* __restrict__ lb,
                          float* __restrict__ out)
{
    __shared__ float slw[LL][H2];
    __shared__ float sg[H2], sb[H2];
    int t = threadIdx.x;
    for (int i = t; i < LL * H2; i += 256) ((float*)slw)[i] = lw[i];
    for (int i = t; i < H2; i += 256) { sg[i] = lng[i]; sb[i] = lnb[i]; }
    __syncthreads();

    int warp = t >> 5, lane = t & 31;
    int m = blockIdx.x * 8 + warp;

    float xv[16];
    const float* xr = X + (size_t)m * H2;
    float s1 = 0.f;
#pragma unroll
    for (int i = 0; i < 16; i++) { xv[i] = xr[i * 32 + lane]; s1 += xv[i]; }
#pragma unroll
    for (int o = 16; o; o >>= 1) s1 += __shfl_xor_sync(0xffffffffu, s1, o);
    float mu = s1 * (1.f / 512.f);
    float s2 = 0.f;
#pragma unroll
    for (int i = 0; i < 16; i++) { float dd = xv[i] - mu; s2 += dd * dd; }
#pragma unroll
    for (int o = 16; o; o >>= 1) s2 += __shfl_xor_sync(0xffffffffu, s2, o);
    float inv = rsqrtf(s2 * (1.f / 512.f) + 1e-5f);

    float xn[16];
#pragma unroll
    for (int i = 0; i < 16; i++) {
        int e = i * 32 + lane;
        xn[i] = (xv[i] - mu) * inv * sg[e] + sb[e];
    }
#pragma unroll
    for (int l = 0; l < LL; l++) {
        float p = 0.f;
#pragma unroll
        for (int i = 0; i < 16; i++) p += xn[i] * slw[l][i * 32 + lane];
#pragma unroll
        for (int o = 16; o; o >>= 1) p += __shfl_xor_sync(0xffffffffu, p, o);
        if (lane == 0) out[(size_t)m * LL + l] = p + lb[l];
    }
}

// ---------------- CRF numerator (one lane per batch) ----------------
__global__ void crf_num(const float* __restrict__ lg,
                        const int* __restrict__ labels,
                        const int* __restrict__ mask,
                        const float* __restrict__ cs,
                        const float* __restrict__ ce,
                        const float* __restrict__ tr)
{
    int b = threadIdx.x;
    if (b >= BB) return;
    const int* lab = labels + b * SS;
    const int* mk  = mask + b * SS;
    const float* e = lg + (size_t)b * SS * LL;
    int tp = lab[0];
    float num = cs[tp] + e[tp];
    int msum = mk[0];
    for (int s = 1; s < SS; s++) {
        int tc = lab[s];
        float m = (float)mk[s];
        num += (tr[tp * LL + tc] + e[s * LL + tc]) * m;
        msum += mk[s];
        tp = tc;
    }
    num += ce[lab[msum - 1]];
    g_num[b] = num;
}

// ---------------- CRF denominator + loss (warp per batch) ----------------
__global__ void crf_denom(const float* __restrict__ lg,
                          const int* __restrict__ mask,
                          const float* __restrict__ cs,
                          const float* __restrict__ ce,
                          const float* __restrict__ tr,
                          float* __restrict__ loss1,
                          float* __restrict__ loss2)
{
    __shared__ float parts[BB];
    __shared__ float str[81];
    int t = threadIdx.x;
    if (t < 81) str[t] = tr[t];
    __syncthreads();

    int warp = t >> 5, lane = t & 31;
    if (warp < BB) {
        int b = warp;
        const float* e = lg + (size_t)b * SS * LL;
        int jj = (lane < LL) ? lane : (LL - 1);
        float alpha = cs[jj] + e[jj];
        for (int s = 1; s < SS; s++) {
            float tv[LL];
            float mx = -1e30f;
#pragma unroll
            for (int i = 0; i < LL; i++) {
                float ai = __shfl_sync(0xffffffffu, alpha, i);
                float v = ai + str[i * LL + jj];
                tv[i] = v;
                mx = fmaxf(mx, v);
            }
            float ssum = 0.f;
#pragma unroll
            for (int i = 0; i < LL; i++) ssum += expf(tv[i] - mx);
            float nxt = mx + logf(ssum) + e[s * LL + jj];
            if (mask[b * SS + s] > 0) alpha = nxt;
        }
        float val = (lane < LL) ? (alpha + ce[jj]) : -1e30f;
        float mx = val;
#pragma unroll
        for (int o = 16; o; o >>= 1) mx = fmaxf(mx, __shfl_xor_sync(0xffffffffu, mx, o));
        float se = expf(val - mx);
#pragma unroll
        for (int o = 16; o; o >>= 1) se += __shfl_xor_sync(0xffffffffu, se, o);
        if (lane == 0) parts[b] = g_num[b] - (mx + logf(se));
    }
    __syncthreads();
    if (t == 0) {
        float s = 0.f;
        for (int i = 0; i < BB; i++) s += parts[i];
        float loss = -s;
        *loss1 = loss;
        if (loss2 != loss1) *loss2 = loss;
    }
}

// ---------------- host launcher ----------------
extern "C" void kernel_launch(void* const* d_in, const int* in_sizes, int n_in,
                              void* d_out, int out_size)
{
    const int*   ids    = (const int*)d_in[0];
    const int*   amask  = (const int*)d_in[1];
    const int*   labels = (const int*)d_in[2];
    const float* emb    = (const float*)d_in[3];
    const float* w_l0   = (const float*)d_in[4];
    const float* w_rest = (const float*)d_in[5];
    const float* w_hh   = (const float*)d_in[6];
    const float* bvec   = (const float*)d_in[7];
    const float* ln_g   = (const float*)d_in[8];
    const float* ln_b   = (const float*)d_in[9];
    const float* lin_w  = (const float*)d_in[10];
    const float* lin_b  = (const float*)d_in[11];
    const float* cstart = (const float*)d_in[12];
    const float* cend   = (const float*)d_in[13];
    const float* ctrans = (const float*)d_in[14];

    float *xa, *xb, *xgp;
    cudaGetSymbolAddress((void**)&xa,  g_xa);
    cudaGetSymbolAddress((void**)&xb,  g_xb);
    cudaGetSymbolAddress((void**)&xgp, g_xg);

    float* outF = (float*)d_out;

    embed_k<<<MTOK, EE>>>(ids, emb, xa);

    float* cur = xa;
    float* nxt = xb;
    for (int layer = 0; layer < 4; layer++) {
        const float* W = (layer == 0) ? w_l0 : (w_rest + (size_t)(layer - 1) * 2 * 1024 * 512);
        int K = (layer == 0) ? EE : H2;
        gemm_xg<<<dim3(NG / 64, MTOK / 128), 256>>>(cur, K, W, bvec + layer * 4096, xgp);
        zero_ctr_k<<<64, 256>>>();   // 64*256 int4 = 65536 ints
        lstm_scan<<<128, 256>>>(xgp, w_hh + (size_t)layer * 2 * 1024 * 256, nxt);
        float* tmp = cur; cur = nxt; nxt = tmp;
    }

    ln_logits<<<MTOK / 8, 256>>>(cur, ln_g, ln_b, lin_w, lin_b, outF);

    crf_num<<<1, 32>>>(outF, labels, amask, cstart, cend, ctrans);

    float* lp1 = outF + (size_t)MTOK * LL;          // expected loss slot (36864)
    float* lp2 = outF + (out_size - 1);             // defensive: last element
    crf_denom<<<1, 512>>>(outF, amask, cstart, cend, ctrans, lp1, lp2);
}